// round 12
// baseline (speedup 1.0000x reference)
#include <cuda_runtime.h>
#include <cuda_bf16.h>
#include <cstdint>

#define DI __device__ __forceinline__

// ---------------------------------------------------------------------------
// Problem:
//   x   : (N=32, C=128, T=512, F=32) fp32
//   out : (N, C, C, F) fp32
//   out[n,i,j,f] = exp(-||x[n,i,:,f]-x[n,j,:,f]||^2 / (2 sigma^2))
//
// R12: SINGLE kernel. Cluster of 8 CTAs = 8 f of one (n, fb). Per chunk,
// CTA rank r loads c-rows [16r,16r+16) of raw x (f32, 8-f cells), converts
// to e4m3 (same cvt as old k1 => same bits), PRMT-transposes, and scatters
// fp8 rows to the peer CTA owning each f via st.shared::cluster. MMA fp8
// gram + exp + DSMEM gather epilogue (R10-proven) write out directly.
// ---------------------------------------------------------------------------
#define NB 32
#define CC 128
#define TT 512
#define FF 32

#define CHUNK    64
#define NCHUNK   8
#define ROW_S    80                      // fp8 stage row stride (64 data + 16)
#define STAGE_B  (128 * ROW_S)           // 10240
#define F32_OFF  (2 * STAGE_B)           // 20480  f32 staging (32 KB)
#define SDIAG_OFF (F32_OFF + 32768)      // 53248
#define SMEM_SZ  (SDIAG_OFF + 512)       // 53760
#define KSTRIDE  272                     // bf16 kern tile row stride (epilogue)
// epilogue kern tile (128*272=34816) reuses [0, F32_OFF+...) after mainloop

DI uint32_t smem_u32(const void* p) {
    uint32_t a;
    asm("{ .reg .u64 t; cvta.to.shared.u64 t, %1; cvt.u32.u64 %0, t; }"
        : "=r"(a) : "l"(p));
    return a;
}
DI uint16_t fp8x2(float hi, float lo) {
    uint16_t r;
    asm("cvt.rn.satfinite.e4m3x2.f32 %0, %1, %2;" : "=h"(r) : "f"(hi), "f"(lo));
    return r;
}
DI void cp16(void* saddr, const void* g) {
    uint32_t a = smem_u32(saddr);
    asm volatile("cp.async.cg.shared.global [%0], [%1], 16;"
                 :: "r"(a), "l"(g) : "memory");
}
DI void cp_commit() { asm volatile("cp.async.commit_group;" ::: "memory"); }
DI void cp_wait_0() { asm volatile("cp.async.wait_group 0;" ::: "memory"); }

DI void mma_fp8(float& c0, float& c1, float& c2, float& c3,
                uint32_t a0, uint32_t a1, uint32_t a2, uint32_t a3,
                uint32_t b0, uint32_t b1) {
    asm volatile(
        "mma.sync.aligned.m16n8k32.row.col.f32.e4m3.e4m3.f32 "
        "{%0,%1,%2,%3}, {%4,%5,%6,%7}, {%8,%9}, {%0,%1,%2,%3};"
        : "+f"(c0), "+f"(c1), "+f"(c2), "+f"(c3)
        : "r"(a0), "r"(a1), "r"(a2), "r"(a3), "r"(b0), "r"(b1));
}
DI void cluster_sync() {
    asm volatile("barrier.cluster.arrive.aligned;" ::: "memory");
    asm volatile("barrier.cluster.wait.aligned;" ::: "memory");
}
DI uint32_t mapa_sh(uint32_t laddr, uint32_t rank) {
    uint32_t r;
    asm("mapa.shared::cluster.u32 %0, %1, %2;" : "=r"(r) : "r"(laddr), "r"(rank));
    return r;
}
DI void sts_remote(uint32_t addr, uint32_t v) {
    asm volatile("st.shared::cluster.u32 [%0], %1;" :: "r"(addr), "r"(v)
                 : "memory");
}
DI void ld_dsmem_v2(uint32_t& a, uint32_t& b, uint32_t addr) {
    asm volatile("ld.shared::cluster.v2.b32 {%0, %1}, [%2];"
                 : "=r"(a), "=r"(b) : "r"(addr));
}
DI void lds128(float& x0, float& y0, float& z0, float& w0, uint32_t a) {
    asm volatile("ld.shared.v4.f32 {%0,%1,%2,%3}, [%4];"
                 : "=f"(x0), "=f"(y0), "=f"(z0), "=f"(w0) : "r"(a));
}

extern "C" __global__ void __launch_bounds__(256, 2) __cluster_dims__(8, 1, 1)
k_gram(const float* __restrict__ x, const float* __restrict__ sigma,
       float* __restrict__ out) {
    extern __shared__ char smem[];
    const uint32_t sb = smem_u32(smem);
    const int tid  = threadIdx.x;
    const int wid  = tid >> 5;
    const int lane = tid & 31;
    const int g    = lane >> 2;
    const int c4   = lane & 3;
    const int bid  = blockIdx.x;
    const int n    = bid >> 5;
    const int fb   = (bid >> 3) & 3;
    const int rank = bid & 7;            // == cluster rank (8 consecutive bids)

    const int RM = (wid >> 2) * 64;
    const int CN = (wid & 3) * 32;

    // scatter roles
    const int tq = lane >> 1;            // 0..15 (t quad)
    const int h  = lane & 1;             // f half (f 0-3 / 4-7)

    float acc[4][4][4];
#pragma unroll
    for (int mt = 0; mt < 4; mt++)
#pragma unroll
        for (int nt = 0; nt < 4; nt++)
#pragma unroll
            for (int r = 0; r < 4; r++) acc[mt][nt][r] = 0.f;

    // x base for this cluster's (n, fb): cell (c, t) -> 8 f floats (32 B)
    const float* xcl = x + (size_t)n * CC * TT * FF + fb * 8;

    // ---- helpers as lambdas (inlined) ----
    auto issue_loads = [&](int k) {
#pragma unroll
        for (int i = 0; i < 8; i++) {
            const int idx = 256 * i + tid;
            const int cl  = idx >> 7;            // c_local 0..15
            const int m   = idx & 127;           // (t_local, half)
            const int tl  = m >> 1;
            const int hh  = m & 1;
            const float* src = xcl
                + ((size_t)(16 * rank + cl) * TT + k * CHUNK + tl) * FF + 4 * hh;
            const uint32_t sig = (uint32_t)(((m & 7) << 4) | (m >> 3));
            cp16(smem + F32_OFF + cl * 2048 + sig * 16, src);
        }
        cp_commit();
    };

    auto scatter = [&](uint32_t stage_off) {
        // read f32 staging, cvt to fp8, transpose t-bytes per f, STS to peers
#pragma unroll
        for (int cp = 0; cp < 2; cp++) {
            const int cl = 2 * wid + cp;         // c_local
            const int c  = 16 * rank + cl;       // global channel row
            const uint32_t fbase = sb + F32_OFF + cl * 2048;
            uint32_t B[4];
#pragma unroll
            for (int q = 0; q < 4; q++) {
                float fx, fy, fz, fw;
                const uint32_t a =
                    fbase + ((uint32_t)(((2 * q + h) << 4) | tq) << 4);
                lds128(fx, fy, fz, fw, a);
                const uint16_t lo  = fp8x2(fy, fx);
                const uint16_t hi2 = fp8x2(fw, fz);
                B[q] = (uint32_t)lo | ((uint32_t)hi2 << 16);
            }
#pragma unroll
            for (int j = 0; j < 4; j++) {
                const uint32_t sel = (uint32_t)(j | ((j + 4) << 4));
                const uint32_t p01 = __byte_perm(B[0], B[1], sel);
                const uint32_t p23 = __byte_perm(B[2], B[3], sel);
                const uint32_t v   = __byte_perm(p01, p23, 0x5410);
                const uint32_t peer = mapa_sh(sb, (uint32_t)(4 * h + j));
                sts_remote(peer + stage_off + (uint32_t)(c * ROW_S + 4 * tq), v);
            }
        }
    };

    auto mma_chunk = [&](uint32_t stage_off) {
        const char* buf = smem + stage_off;
#pragma unroll
        for (int ks = 0; ks < 2; ks++) {
            const int kb = ks * 32 + c4 * 4;
            uint32_t af[4][4];
#pragma unroll
            for (int mt = 0; mt < 4; mt++) {
                const char* r0 = buf + (RM + mt * 16 + g) * ROW_S;
                af[mt][0] = *(const uint32_t*)(r0 + kb);
                af[mt][1] = *(const uint32_t*)(r0 + 8 * ROW_S + kb);
                af[mt][2] = *(const uint32_t*)(r0 + kb + 16);
                af[mt][3] = *(const uint32_t*)(r0 + 8 * ROW_S + kb + 16);
            }
            uint32_t bf[4][2];
#pragma unroll
            for (int nt = 0; nt < 4; nt++) {
                const char* r0 = buf + (CN + nt * 8 + g) * ROW_S;
                bf[nt][0] = *(const uint32_t*)(r0 + kb);
                bf[nt][1] = *(const uint32_t*)(r0 + kb + 16);
            }
#pragma unroll
            for (int mt = 0; mt < 4; mt++)
#pragma unroll
                for (int nt = 0; nt < 4; nt++)
                    mma_fp8(acc[mt][nt][0], acc[mt][nt][1],
                            acc[mt][nt][2], acc[mt][nt][3],
                            af[mt][0], af[mt][1], af[mt][2], af[mt][3],
                            bf[nt][0], bf[nt][1]);
        }
    };

    // ---- prologue: distribute chunk 0 ----
    issue_loads(0);
    cp_wait_0();
    __syncthreads();
    scatter(0);
    cluster_sync();

    // ---- mainloop ----
#pragma unroll 1
    for (int k = 0; k < NCHUNK; k++) {
        if (k + 1 < NCHUNK) issue_loads(k + 1);
        mma_chunk((uint32_t)((k & 1) * STAGE_B));
        if (k + 1 < NCHUNK) {
            cp_wait_0();
            __syncthreads();
            scatter((uint32_t)(((k + 1) & 1) * STAGE_B));
            cluster_sync();
        }
    }

    // ---- epilogue (R10-proven): exp -> bf16 kern tile, DSMEM gather ----
    float* sdiag = reinterpret_cast<float*>(smem + SDIAG_OFF);

#pragma unroll
    for (int mt = 0; mt < 4; mt++)
#pragma unroll
        for (int nt = 0; nt < 4; nt++)
#pragma unroll
            for (int r = 0; r < 4; r++) {
                const int i = RM + mt * 16 + g + ((r >> 1) << 3);
                const int j = CN + nt * 8 + c4 * 2 + (r & 1);
                if (i == j) sdiag[i] = acc[mt][nt][r];
            }
    __syncthreads();          // all warps past MMA; stage area reusable

    const float sg   = sigma[0];
    const float ninv = -0.5f / (sg * sg);

    float dj[4][2];
#pragma unroll
    for (int nt = 0; nt < 4; nt++) {
        dj[nt][0] = sdiag[CN + nt * 8 + c4 * 2];
        dj[nt][1] = sdiag[CN + nt * 8 + c4 * 2 + 1];
    }

#pragma unroll
    for (int mt = 0; mt < 4; mt++) {
#pragma unroll
        for (int rh = 0; rh < 2; rh++) {
            const int i  = RM + mt * 16 + g + rh * 8;
            const float di = sdiag[i];
            char* row = smem + i * KSTRIDE;
#pragma unroll
            for (int nt = 0; nt < 4; nt++) {
                const int j0 = CN + nt * 8 + c4 * 2;
                const float g0 = acc[mt][nt][rh * 2 + 0];
                const float g1 = acc[mt][nt][rh * 2 + 1];
                const float a0 = fmaxf(di + dj[nt][0] - 2.0f * g0, 0.0f) * ninv;
                const float a1 = fmaxf(di + dj[nt][1] - 2.0f * g1, 0.0f) * ninv;
                float v0 = 0.0f, v1 = 0.0f;
                if (a0 > -105.0f) v0 = __expf(a0);   // underflow -> exact 0
                if (a1 > -105.0f) v1 = __expf(a1);
                __nv_bfloat162 p = __floats2bfloat162_rn(v0, v1);
                *reinterpret_cast<uint32_t*>(row + j0 * 2) =
                    *reinterpret_cast<uint32_t*>(&p);
            }
        }
    }
    __syncthreads();
    cluster_sync();        // all 8 kern tiles visible cluster-wide

    // rank owns rows [16*rank, 16*rank+16); lane: fr = lane&7 -> peer (f),
    // jq = lane>>3 -> j quad
    const uint32_t fr = (uint32_t)(lane & 7);
    const int      jq = lane >> 3;
    const uint32_t peer = mapa_sh(sb, fr);

    float* ob = out + ((size_t)n * CC * CC) * FF + fb * 8 + fr;

#pragma unroll
    for (int ih = 0; ih < 2; ih++) {
        const int i = rank * 16 + wid * 2 + ih;
        const uint32_t prow = peer + (uint32_t)i * KSTRIDE;
        float* orow = ob + (size_t)i * CC * FF;
#pragma unroll
        for (int jb = 0; jb < 128; jb += 16) {
            const int j = jb + jq * 4;
            uint32_t w0, w1;
            ld_dsmem_v2(w0, w1, prow + (uint32_t)j * 2);   // 4 bf16: j..j+3
            orow[(size_t)(j + 0) * FF] = __uint_as_float(w0 << 16);
            orow[(size_t)(j + 1) * FF] = __uint_as_float(w0 & 0xFFFF0000u);
            orow[(size_t)(j + 2) * FF] = __uint_as_float(w1 << 16);
            orow[(size_t)(j + 3) * FF] = __uint_as_float(w1 & 0xFFFF0000u);
        }
    }

    cluster_sync();        // nobody exits while peers read our smem
}

// ---------------------------------------------------------------------------
// launch: ONE kernel
// ---------------------------------------------------------------------------
extern "C" void kernel_launch(void* const* d_in, const int* in_sizes, int n_in,
                              void* d_out, int out_size) {
    const float* x     = (const float*)d_in[0];
    const float* sigma = (const float*)d_in[1];
    float* out         = (float*)d_out;
    (void)in_sizes; (void)n_in; (void)out_size;

    cudaFuncSetAttribute(k_gram, cudaFuncAttributeMaxDynamicSharedMemorySize,
                         SMEM_SZ);
    k_gram<<<NB * FF, 256, SMEM_SZ>>>(x, sigma, out);
}

// round 13
// speedup vs baseline: 1.0037x; 1.0037x over previous
#include <cuda_runtime.h>
#include <cuda_bf16.h>
#include <cstdint>

#define DI __device__ __forceinline__

// ---------------------------------------------------------------------------
// Problem:
//   x   : (N=32, C=128, T=512, F=32) fp32
//   out : (N, C, C, F) fp32
//   out[n,i,j,f] = exp(-||x[n,i,:,f]-x[n,j,:,f]||^2 / (2 sigma^2))
//
// R12: SINGLE kernel. Cluster of 8 CTAs = 8 f of one (n, fb). Per chunk,
// CTA rank r loads c-rows [16r,16r+16) of raw x (f32, 8-f cells), converts
// to e4m3 (same cvt as old k1 => same bits), PRMT-transposes, and scatters
// fp8 rows to the peer CTA owning each f via st.shared::cluster. MMA fp8
// gram + exp + DSMEM gather epilogue (R10-proven) write out directly.
// ---------------------------------------------------------------------------
#define NB 32
#define CC 128
#define TT 512
#define FF 32

#define CHUNK    64
#define NCHUNK   8
#define ROW_S    80                      // fp8 stage row stride (64 data + 16)
#define STAGE_B  (128 * ROW_S)           // 10240
#define F32_OFF  (2 * STAGE_B)           // 20480  f32 staging (32 KB)
#define SDIAG_OFF (F32_OFF + 32768)      // 53248
#define SMEM_SZ  (SDIAG_OFF + 512)       // 53760
#define KSTRIDE  272                     // bf16 kern tile row stride (epilogue)
// epilogue kern tile (128*272=34816) reuses [0, F32_OFF+...) after mainloop

DI uint32_t smem_u32(const void* p) {
    uint32_t a;
    asm("{ .reg .u64 t; cvta.to.shared.u64 t, %1; cvt.u32.u64 %0, t; }"
        : "=r"(a) : "l"(p));
    return a;
}
DI uint16_t fp8x2(float hi, float lo) {
    uint16_t r;
    asm("cvt.rn.satfinite.e4m3x2.f32 %0, %1, %2;" : "=h"(r) : "f"(hi), "f"(lo));
    return r;
}
DI void cp16(void* saddr, const void* g) {
    uint32_t a = smem_u32(saddr);
    asm volatile("cp.async.cg.shared.global [%0], [%1], 16;"
                 :: "r"(a), "l"(g) : "memory");
}
DI void cp_commit() { asm volatile("cp.async.commit_group;" ::: "memory"); }
DI void cp_wait_0() { asm volatile("cp.async.wait_group 0;" ::: "memory"); }

DI void mma_fp8(float& c0, float& c1, float& c2, float& c3,
                uint32_t a0, uint32_t a1, uint32_t a2, uint32_t a3,
                uint32_t b0, uint32_t b1) {
    asm volatile(
        "mma.sync.aligned.m16n8k32.row.col.f32.e4m3.e4m3.f32 "
        "{%0,%1,%2,%3}, {%4,%5,%6,%7}, {%8,%9}, {%0,%1,%2,%3};"
        : "+f"(c0), "+f"(c1), "+f"(c2), "+f"(c3)
        : "r"(a0), "r"(a1), "r"(a2), "r"(a3), "r"(b0), "r"(b1));
}
DI void cluster_sync() {
    asm volatile("barrier.cluster.arrive.aligned;" ::: "memory");
    asm volatile("barrier.cluster.wait.aligned;" ::: "memory");
}
DI uint32_t mapa_sh(uint32_t laddr, uint32_t rank) {
    uint32_t r;
    asm("mapa.shared::cluster.u32 %0, %1, %2;" : "=r"(r) : "r"(laddr), "r"(rank));
    return r;
}
DI void sts_remote(uint32_t addr, uint32_t v) {
    asm volatile("st.shared::cluster.u32 [%0], %1;" :: "r"(addr), "r"(v)
                 : "memory");
}
DI void ld_dsmem_v2(uint32_t& a, uint32_t& b, uint32_t addr) {
    asm volatile("ld.shared::cluster.v2.b32 {%0, %1}, [%2];"
                 : "=r"(a), "=r"(b) : "r"(addr));
}
DI void lds128(float& x0, float& y0, float& z0, float& w0, uint32_t a) {
    asm volatile("ld.shared.v4.f32 {%0,%1,%2,%3}, [%4];"
                 : "=f"(x0), "=f"(y0), "=f"(z0), "=f"(w0) : "r"(a));
}

extern "C" __global__ void __launch_bounds__(256, 2) __cluster_dims__(8, 1, 1)
k_gram(const float* __restrict__ x, const float* __restrict__ sigma,
       float* __restrict__ out) {
    extern __shared__ char smem[];
    const uint32_t sb = smem_u32(smem);
    const int tid  = threadIdx.x;
    const int wid  = tid >> 5;
    const int lane = tid & 31;
    const int g    = lane >> 2;
    const int c4   = lane & 3;
    const int bid  = blockIdx.x;
    const int n    = bid >> 5;
    const int fb   = (bid >> 3) & 3;
    const int rank = bid & 7;            // == cluster rank (8 consecutive bids)

    const int RM = (wid >> 2) * 64;
    const int CN = (wid & 3) * 32;

    // scatter roles
    const int tq = lane >> 1;            // 0..15 (t quad)
    const int h  = lane & 1;             // f half (f 0-3 / 4-7)

    float acc[4][4][4];
#pragma unroll
    for (int mt = 0; mt < 4; mt++)
#pragma unroll
        for (int nt = 0; nt < 4; nt++)
#pragma unroll
            for (int r = 0; r < 4; r++) acc[mt][nt][r] = 0.f;

    // x base for this cluster's (n, fb): cell (c, t) -> 8 f floats (32 B)
    const float* xcl = x + (size_t)n * CC * TT * FF + fb * 8;

    // ---- helpers as lambdas (inlined) ----
    auto issue_loads = [&](int k) {
#pragma unroll
        for (int i = 0; i < 8; i++) {
            const int idx = 256 * i + tid;
            const int cl  = idx >> 7;            // c_local 0..15
            const int m   = idx & 127;           // (t_local, half)
            const int tl  = m >> 1;
            const int hh  = m & 1;
            const float* src = xcl
                + ((size_t)(16 * rank + cl) * TT + k * CHUNK + tl) * FF + 4 * hh;
            const uint32_t sig = (uint32_t)(((m & 7) << 4) | (m >> 3));
            cp16(smem + F32_OFF + cl * 2048 + sig * 16, src);
        }
        cp_commit();
    };

    auto scatter = [&](uint32_t stage_off) {
        // read f32 staging, cvt to fp8, transpose t-bytes per f, STS to peers
#pragma unroll
        for (int cp = 0; cp < 2; cp++) {
            const int cl = 2 * wid + cp;         // c_local
            const int c  = 16 * rank + cl;       // global channel row
            const uint32_t fbase = sb + F32_OFF + cl * 2048;
            uint32_t B[4];
#pragma unroll
            for (int q = 0; q < 4; q++) {
                float fx, fy, fz, fw;
                const uint32_t a =
                    fbase + ((uint32_t)(((2 * q + h) << 4) | tq) << 4);
                lds128(fx, fy, fz, fw, a);
                const uint16_t lo  = fp8x2(fy, fx);
                const uint16_t hi2 = fp8x2(fw, fz);
                B[q] = (uint32_t)lo | ((uint32_t)hi2 << 16);
            }
#pragma unroll
            for (int j = 0; j < 4; j++) {
                const uint32_t sel = (uint32_t)(j | ((j + 4) << 4));
                const uint32_t p01 = __byte_perm(B[0], B[1], sel);
                const uint32_t p23 = __byte_perm(B[2], B[3], sel);
                const uint32_t v   = __byte_perm(p01, p23, 0x5410);
                const uint32_t peer = mapa_sh(sb, (uint32_t)(4 * h + j));
                sts_remote(peer + stage_off + (uint32_t)(c * ROW_S + 4 * tq), v);
            }
        }
    };

    auto mma_chunk = [&](uint32_t stage_off) {
        const char* buf = smem + stage_off;
#pragma unroll
        for (int ks = 0; ks < 2; ks++) {
            const int kb = ks * 32 + c4 * 4;
            uint32_t af[4][4];
#pragma unroll
            for (int mt = 0; mt < 4; mt++) {
                const char* r0 = buf + (RM + mt * 16 + g) * ROW_S;
                af[mt][0] = *(const uint32_t*)(r0 + kb);
                af[mt][1] = *(const uint32_t*)(r0 + 8 * ROW_S + kb);
                af[mt][2] = *(const uint32_t*)(r0 + kb + 16);
                af[mt][3] = *(const uint32_t*)(r0 + 8 * ROW_S + kb + 16);
            }
            uint32_t bf[4][2];
#pragma unroll
            for (int nt = 0; nt < 4; nt++) {
                const char* r0 = buf + (CN + nt * 8 + g) * ROW_S;
                bf[nt][0] = *(const uint32_t*)(r0 + kb);
                bf[nt][1] = *(const uint32_t*)(r0 + kb + 16);
            }
#pragma unroll
            for (int mt = 0; mt < 4; mt++)
#pragma unroll
                for (int nt = 0; nt < 4; nt++)
                    mma_fp8(acc[mt][nt][0], acc[mt][nt][1],
                            acc[mt][nt][2], acc[mt][nt][3],
                            af[mt][0], af[mt][1], af[mt][2], af[mt][3],
                            bf[nt][0], bf[nt][1]);
        }
    };

    // ---- prologue: distribute chunk 0 ----
    issue_loads(0);
    cp_wait_0();
    __syncthreads();
    scatter(0);
    cluster_sync();

    // ---- mainloop ----
#pragma unroll 1
    for (int k = 0; k < NCHUNK; k++) {
        if (k + 1 < NCHUNK) issue_loads(k + 1);
        mma_chunk((uint32_t)((k & 1) * STAGE_B));
        if (k + 1 < NCHUNK) {
            cp_wait_0();
            __syncthreads();
            scatter((uint32_t)(((k + 1) & 1) * STAGE_B));
            cluster_sync();
        }
    }

    // ---- epilogue (R10-proven): exp -> bf16 kern tile, DSMEM gather ----
    float* sdiag = reinterpret_cast<float*>(smem + SDIAG_OFF);

#pragma unroll
    for (int mt = 0; mt < 4; mt++)
#pragma unroll
        for (int nt = 0; nt < 4; nt++)
#pragma unroll
            for (int r = 0; r < 4; r++) {
                const int i = RM + mt * 16 + g + ((r >> 1) << 3);
                const int j = CN + nt * 8 + c4 * 2 + (r & 1);
                if (i == j) sdiag[i] = acc[mt][nt][r];
            }
    __syncthreads();          // all warps past MMA; stage area reusable

    const float sg   = sigma[0];
    const float ninv = -0.5f / (sg * sg);

    float dj[4][2];
#pragma unroll
    for (int nt = 0; nt < 4; nt++) {
        dj[nt][0] = sdiag[CN + nt * 8 + c4 * 2];
        dj[nt][1] = sdiag[CN + nt * 8 + c4 * 2 + 1];
    }

#pragma unroll
    for (int mt = 0; mt < 4; mt++) {
#pragma unroll
        for (int rh = 0; rh < 2; rh++) {
            const int i  = RM + mt * 16 + g + rh * 8;
            const float di = sdiag[i];
            char* row = smem + i * KSTRIDE;
#pragma unroll
            for (int nt = 0; nt < 4; nt++) {
                const int j0 = CN + nt * 8 + c4 * 2;
                const float g0 = acc[mt][nt][rh * 2 + 0];
                const float g1 = acc[mt][nt][rh * 2 + 1];
                const float a0 = fmaxf(di + dj[nt][0] - 2.0f * g0, 0.0f) * ninv;
                const float a1 = fmaxf(di + dj[nt][1] - 2.0f * g1, 0.0f) * ninv;
                float v0 = 0.0f, v1 = 0.0f;
                if (a0 > -105.0f) v0 = __expf(a0);   // underflow -> exact 0
                if (a1 > -105.0f) v1 = __expf(a1);
                __nv_bfloat162 p = __floats2bfloat162_rn(v0, v1);
                *reinterpret_cast<uint32_t*>(row + j0 * 2) =
                    *reinterpret_cast<uint32_t*>(&p);
            }
        }
    }
    __syncthreads();
    cluster_sync();        // all 8 kern tiles visible cluster-wide

    // rank owns rows [16*rank, 16*rank+16); lane: fr = lane&7 -> peer (f),
    // jq = lane>>3 -> j quad
    const uint32_t fr = (uint32_t)(lane & 7);
    const int      jq = lane >> 3;
    const uint32_t peer = mapa_sh(sb, fr);

    float* ob = out + ((size_t)n * CC * CC) * FF + fb * 8 + fr;

#pragma unroll
    for (int ih = 0; ih < 2; ih++) {
        const int i = rank * 16 + wid * 2 + ih;
        const uint32_t prow = peer + (uint32_t)i * KSTRIDE;
        float* orow = ob + (size_t)i * CC * FF;
#pragma unroll
        for (int jb = 0; jb < 128; jb += 16) {
            const int j = jb + jq * 4;
            uint32_t w0, w1;
            ld_dsmem_v2(w0, w1, prow + (uint32_t)j * 2);   // 4 bf16: j..j+3
            orow[(size_t)(j + 0) * FF] = __uint_as_float(w0 << 16);
            orow[(size_t)(j + 1) * FF] = __uint_as_float(w0 & 0xFFFF0000u);
            orow[(size_t)(j + 2) * FF] = __uint_as_float(w1 << 16);
            orow[(size_t)(j + 3) * FF] = __uint_as_float(w1 & 0xFFFF0000u);
        }
    }

    cluster_sync();        // nobody exits while peers read our smem
}

// ---------------------------------------------------------------------------
// launch: ONE kernel
// ---------------------------------------------------------------------------
extern "C" void kernel_launch(void* const* d_in, const int* in_sizes, int n_in,
                              void* d_out, int out_size) {
    const float* x     = (const float*)d_in[0];
    const float* sigma = (const float*)d_in[1];
    float* out         = (float*)d_out;
    (void)in_sizes; (void)n_in; (void)out_size;

    cudaFuncSetAttribute(k_gram, cudaFuncAttributeMaxDynamicSharedMemorySize,
                         SMEM_SZ);
    k_gram<<<NB * FF, 256, SMEM_SZ>>>(x, sigma, out);
}

// round 14
// speedup vs baseline: 1.2502x; 1.2456x over previous
#include <cuda_runtime.h>
#include <cuda_bf16.h>
#include <cstdint>

#define DI __device__ __forceinline__

// ---------------------------------------------------------------------------
// Problem:
//   x   : (N=32, C=128, T=512, F=32) fp32
//   out : (N, C, C, F) fp32
//   out[n,i,j,f] = exp(-||x[n,i,:,f]-x[n,j,:,f]||^2 / (2 sigma^2))
//
// R13: R10 kernel bodies UNCHANGED; n-range split into 4 chunks pipelined
// across two streams inside the captured graph:
//   s0:  k1(0) -> k1(1) -> k1(2) -> k1(3)
//   s1:       gram(0) -> gram(1) -> gram(2) -> gram(3)
// gram(i) waits on event after k1(i); k1(i+1) overlaps gram(i).
// ---------------------------------------------------------------------------
#define NB 32
#define CC 128
#define TT 512
#define FF 32

#define NCHB 4            // n-chunks in the pipeline
#define NPC  (NB / NCHB)  // 8 n per chunk

__device__ __align__(256) unsigned char g_x8[(size_t)NB * FF * CC * TT]; // 64 MiB

DI uint16_t fp8x2(float hi, float lo) {
    uint16_t r;
    asm("cvt.rn.satfinite.e4m3x2.f32 %0, %1, %2;" : "=h"(r) : "f"(hi), "f"(lo));
    return r;
}

// ---------------------------------------------------------------------------
// Kernel 1: (N,C,T,F) fp32 -> (N,F,C,T) e4m3.  Tile 64t x 32f. (R10 body)
// grid (T/64, C, NPC); n = n_base + blockIdx.z
// ---------------------------------------------------------------------------
__global__ void __launch_bounds__(256) k_transpose(const float* __restrict__ x,
                                                   int n_base) {
    __shared__ float tile[64][33];
    const int t0 = blockIdx.x * 64;
    const int c  = blockIdx.y;
    const int n  = n_base + blockIdx.z;
    const int lane = threadIdx.x;

    const float* src = x + (((size_t)(n * CC + c)) * TT + t0) * FF;
#pragma unroll
    for (int it = 0; it < 8; it++) {
        int t = threadIdx.y + it * 8;
        tile[t][lane] = src[(size_t)t * FF + lane];
    }
    __syncthreads();

#pragma unroll
    for (int it = 0; it < 4; it++) {
        int fi = threadIdx.y + it * 8;
        uint16_t p = fp8x2(tile[2 * lane + 1][fi], tile[2 * lane][fi]);
        *reinterpret_cast<uint16_t*>(
            g_x8 + (((size_t)(n * FF + fi)) * CC + c) * TT + t0 + 2 * lane) = p;
    }
}

// ---------------------------------------------------------------------------
// Kernel 2: fp8 gram + cluster(8) DSMEM epilogue -> direct out stores
// grid = NPC*32 = 256 per chunk (cluster 8 = the 8 f of one (n, fb))
// (R10 body; only n_base added)
// ---------------------------------------------------------------------------
#define CHUNK      128
#define NCHUNK     4
#define ROW_BYTES  144
#define STAGE_B    (128 * ROW_BYTES)        // 18432
#define SDIAG_OFF  (3 * STAGE_B)            // 55296
#define SMEM_SZ    (SDIAG_OFF + 128 * 4)    // 55808
#define KSTRIDE    272                      // bf16 kern tile row stride
// kern tile (128*272 = 34816 B) reuses stage area post-mainloop

DI uint32_t smem_u32(const void* p) {
    uint32_t a;
    asm("{ .reg .u64 t; cvta.to.shared.u64 t, %1; cvt.u32.u64 %0, t; }"
        : "=r"(a) : "l"(p));
    return a;
}
DI void cp16(void* saddr, const void* g) {
    uint32_t a = smem_u32(saddr);
    asm volatile("cp.async.cg.shared.global [%0], [%1], 16;"
                 :: "r"(a), "l"(g) : "memory");
}
DI void cp_commit() { asm volatile("cp.async.commit_group;" ::: "memory"); }
DI void cp_wait_2() { asm volatile("cp.async.wait_group 2;" ::: "memory"); }

DI void mma_fp8(float& c0, float& c1, float& c2, float& c3,
                uint32_t a0, uint32_t a1, uint32_t a2, uint32_t a3,
                uint32_t b0, uint32_t b1) {
    asm volatile(
        "mma.sync.aligned.m16n8k32.row.col.f32.e4m3.e4m3.f32 "
        "{%0,%1,%2,%3}, {%4,%5,%6,%7}, {%8,%9}, {%0,%1,%2,%3};"
        : "+f"(c0), "+f"(c1), "+f"(c2), "+f"(c3)
        : "r"(a0), "r"(a1), "r"(a2), "r"(a3), "r"(b0), "r"(b1));
}

DI void cluster_sync() {
    asm volatile("barrier.cluster.arrive.aligned;" ::: "memory");
    asm volatile("barrier.cluster.wait.aligned;" ::: "memory");
}
DI uint32_t cluster_rank() {
    uint32_t r;
    asm("mov.u32 %0, %%cluster_ctarank;" : "=r"(r));
    return r;
}
DI uint32_t mapa_sh(uint32_t laddr, uint32_t rank) {
    uint32_t r;
    asm("mapa.shared::cluster.u32 %0, %1, %2;" : "=r"(r) : "r"(laddr), "r"(rank));
    return r;
}
DI void ld_dsmem_v2(uint32_t& a, uint32_t& b, uint32_t addr) {
    asm volatile("ld.shared::cluster.v2.b32 {%0, %1}, [%2];"
                 : "=r"(a), "=r"(b) : "r"(addr));
}

DI void load_chunk(const unsigned char* A, char* buf, int tid, int k0) {
    const int row  = tid >> 1;
    const int half = tid & 1;
    const unsigned char* g = A + (size_t)row * TT + k0 + half * 64;
    char* s = buf + row * ROW_BYTES + half * 64;
#pragma unroll
    for (int v = 0; v < 4; v++)
        cp16(s + v * 16, g + v * 16);
}

extern "C" __global__ void __launch_bounds__(256, 2) __cluster_dims__(8, 1, 1)
k_gram(const float* __restrict__ sigma, float* __restrict__ out, int n_base) {
    extern __shared__ char smem[];
    const uint32_t sb = smem_u32(smem);
    const int tid  = threadIdx.x;
    const int wid  = tid >> 5;
    const int lane = tid & 31;
    const int g    = lane >> 2;
    const int c4   = lane & 3;
    const int gbid = n_base * 32 + blockIdx.x;   // global (n,f) id
    const int n    = gbid >> 5;
    const int fb   = (gbid >> 3) & 3;

    const int RM = (wid >> 2) * 64;
    const int CN = (wid & 3) * 32;

    const unsigned char* A = g_x8 + (size_t)gbid * CC * TT;

    float acc[4][4][4];
#pragma unroll
    for (int mt = 0; mt < 4; mt++)
#pragma unroll
        for (int nt = 0; nt < 4; nt++)
#pragma unroll
            for (int r = 0; r < 4; r++) acc[mt][nt][r] = 0.f;

    // ---- mainloop (R10-proven) ----
    load_chunk(A, smem + 0 * STAGE_B, tid, 0 * CHUNK);
    cp_commit();
    load_chunk(A, smem + 1 * STAGE_B, tid, 1 * CHUNK);
    cp_commit();

#pragma unroll 1
    for (int k = 0; k < NCHUNK; k++) {
        if (k + 2 < NCHUNK)
            load_chunk(A, smem + ((k + 2) % 3) * STAGE_B, tid, (k + 2) * CHUNK);
        cp_commit();
        cp_wait_2();
        __syncthreads();

        const char* buf = smem + (k % 3) * STAGE_B;
#pragma unroll
        for (int ks = 0; ks < 4; ks++) {
            const int kb = ks * 32 + c4 * 4;
            uint32_t af[4][4];
#pragma unroll
            for (int mt = 0; mt < 4; mt++) {
                const char* r0 = buf + (RM + mt * 16 + g) * ROW_BYTES;
                af[mt][0] = *(const uint32_t*)(r0 + kb);
                af[mt][1] = *(const uint32_t*)(r0 + 8 * ROW_BYTES + kb);
                af[mt][2] = *(const uint32_t*)(r0 + kb + 16);
                af[mt][3] = *(const uint32_t*)(r0 + 8 * ROW_BYTES + kb + 16);
            }
            uint32_t bf[4][2];
#pragma unroll
            for (int nt = 0; nt < 4; nt++) {
                const char* r0 = buf + (CN + nt * 8 + g) * ROW_BYTES;
                bf[nt][0] = *(const uint32_t*)(r0 + kb);
                bf[nt][1] = *(const uint32_t*)(r0 + kb + 16);
            }
#pragma unroll
            for (int mt = 0; mt < 4; mt++)
#pragma unroll
                for (int nt = 0; nt < 4; nt++)
                    mma_fp8(acc[mt][nt][0], acc[mt][nt][1],
                            acc[mt][nt][2], acc[mt][nt][3],
                            af[mt][0], af[mt][1], af[mt][2], af[mt][3],
                            bf[nt][0], bf[nt][1]);
        }
        __syncthreads();
    }

    // ---- epilogue: exp -> bf16 kern tile in OWN smem ----
    float* sdiag = reinterpret_cast<float*>(smem + SDIAG_OFF);

#pragma unroll
    for (int mt = 0; mt < 4; mt++)
#pragma unroll
        for (int nt = 0; nt < 4; nt++)
#pragma unroll
            for (int r = 0; r < 4; r++) {
                const int i = RM + mt * 16 + g + ((r >> 1) << 3);
                const int j = CN + nt * 8 + c4 * 2 + (r & 1);
                if (i == j) sdiag[i] = acc[mt][nt][r];
            }
    __syncthreads();

    const float sg   = sigma[0];
    const float ninv = -0.5f / (sg * sg);

    float dj[4][2];
#pragma unroll
    for (int nt = 0; nt < 4; nt++) {
        dj[nt][0] = sdiag[CN + nt * 8 + c4 * 2];
        dj[nt][1] = sdiag[CN + nt * 8 + c4 * 2 + 1];
    }

#pragma unroll
    for (int mt = 0; mt < 4; mt++) {
#pragma unroll
        for (int rh = 0; rh < 2; rh++) {
            const int i  = RM + mt * 16 + g + rh * 8;
            const float di = sdiag[i];
            char* row = smem + i * KSTRIDE;
#pragma unroll
            for (int nt = 0; nt < 4; nt++) {
                const int j0 = CN + nt * 8 + c4 * 2;
                const float g0 = acc[mt][nt][rh * 2 + 0];
                const float g1 = acc[mt][nt][rh * 2 + 1];
                const float a0 = fmaxf(di + dj[nt][0] - 2.0f * g0, 0.0f) * ninv;
                const float a1 = fmaxf(di + dj[nt][1] - 2.0f * g1, 0.0f) * ninv;
                float v0 = 0.0f, v1 = 0.0f;
                if (a0 > -105.0f) v0 = __expf(a0);   // underflow -> exact 0
                if (a1 > -105.0f) v1 = __expf(a1);
                __nv_bfloat162 p = __floats2bfloat162_rn(v0, v1);
                *reinterpret_cast<uint32_t*>(row + j0 * 2) =
                    *reinterpret_cast<uint32_t*>(&p);
            }
        }
    }
    __syncthreads();
    cluster_sync();        // all 8 kern tiles visible cluster-wide

    // ---- DSMEM gather + direct coalesced stores (R10-proven) ----
    const uint32_t rank = cluster_rank();
    const uint32_t fr   = (uint32_t)(lane & 7);
    const int      jq   = lane >> 3;
    const uint32_t peer = mapa_sh(sb, fr);

    float* ob = out + ((size_t)n * CC * CC) * FF + fb * 8 + fr;

#pragma unroll
    for (int ih = 0; ih < 2; ih++) {
        const int i = (int)rank * 16 + wid * 2 + ih;
        const uint32_t prow = peer + (uint32_t)i * KSTRIDE;
        float* orow = ob + (size_t)i * CC * FF;
#pragma unroll
        for (int jb = 0; jb < 128; jb += 16) {
            const int j = jb + jq * 4;
            uint32_t w0, w1;
            ld_dsmem_v2(w0, w1, prow + (uint32_t)j * 2);   // 4 bf16: j..j+3
            orow[(size_t)(j + 0) * FF] = __uint_as_float(w0 << 16);
            orow[(size_t)(j + 1) * FF] = __uint_as_float(w0 & 0xFFFF0000u);
            orow[(size_t)(j + 2) * FF] = __uint_as_float(w1 << 16);
            orow[(size_t)(j + 3) * FF] = __uint_as_float(w1 & 0xFFFF0000u);
        }
    }

    cluster_sync();        // nobody exits while peers read our smem
}

// ---------------------------------------------------------------------------
// launch: 4-chunk two-stream pipeline inside the captured graph
// ---------------------------------------------------------------------------
extern "C" void kernel_launch(void* const* d_in, const int* in_sizes, int n_in,
                              void* d_out, int out_size) {
    const float* x     = (const float*)d_in[0];
    const float* sigma = (const float*)d_in[1];
    float* out         = (float*)d_out;
    (void)in_sizes; (void)n_in; (void)out_size;

    cudaFuncSetAttribute(k_gram, cudaFuncAttributeMaxDynamicSharedMemorySize,
                         SMEM_SZ);

    // host-side objects only (no device memory); created per call, leaked
    // (kernel_launch runs twice: correctness + capture)
    cudaStream_t s1;
    cudaStreamCreateWithFlags(&s1, cudaStreamNonBlocking);
    cudaEvent_t ev[NCHB], done;
    for (int i = 0; i < NCHB; i++)
        cudaEventCreateWithFlags(&ev[i], cudaEventDisableTiming);
    cudaEventCreateWithFlags(&done, cudaEventDisableTiming);

    dim3 g1(TT / 64, CC, NPC), b1(32, 8);
    for (int i = 0; i < NCHB; i++) {
        k_transpose<<<g1, b1>>>(x, i * NPC);         // capture (default) stream
        cudaEventRecord(ev[i], 0);
        cudaStreamWaitEvent(s1, ev[i], 0);
        k_gram<<<NPC * 32, 256, SMEM_SZ, s1>>>(sigma, out, i * NPC);
    }
    cudaEventRecord(done, s1);
    cudaStreamWaitEvent(0, done, 0);                 // rejoin capture stream
}